// round 7
// baseline (speedup 1.0000x reference)
#include <cuda_runtime.h>
#include <math.h>
#include <cstdint>

#define MAXN   50000
#define MAXE   10000
#define MAXNNZ 600000

// ---------------- scratch (static __device__, no allocations) ----------------
__device__ float g_xh[MAXN * 256];    // x @ W1
__device__ float g_ax[MAXN * 4];
__device__ float g_ae[MAXE * 4];
__device__ float g_A1[128 * 4];
__device__ float g_A2[128 * 4];
__device__ float g_alpha[MAXNNZ * 4];
__device__ float g_eh[MAXE * 256];
__device__ float g_xh2[MAXN * 64];    // fused: elu(node1 out) @ W2
__device__ float g_eh2[MAXE * 64];
__device__ int g_cntN[MAXN], g_cntE[MAXE];
__device__ int g_curN[MAXN], g_curE[MAXE];
__device__ int g_offN[MAXN], g_offE[MAXE];
__device__ int g_csrN[MAXNNZ], g_csrE[MAXNNZ];
__device__ int g_totN, g_totE;

// ---------------- CSR construction ----------------
__global__ void zero_counts_kernel(int N, int E) {
    int i = blockIdx.x * blockDim.x + threadIdx.x;
    int s = gridDim.x * blockDim.x;
    if (i == 0) { g_totN = 0; g_totE = 0; }
    for (int j = i; j < N; j += s) { g_cntN[j] = 0; g_curN[j] = 0; }
    for (int j = i; j < E; j += s) { g_cntE[j] = 0; g_curE[j] = 0; }
}

__global__ void count_kernel(const int* __restrict__ node, const int* __restrict__ hedge, int nnz) {
    int t = blockIdx.x * blockDim.x + threadIdx.x;
    int stride4 = gridDim.x * blockDim.x * 4;
    for (int j0 = t * 4; j0 < nnz; j0 += stride4) {
        if (j0 + 3 < nnz) {
            int4 n4 = *(const int4*)&node[j0];
            int4 h4 = *(const int4*)&hedge[j0];
            atomicAdd(&g_cntN[n4.x], 1); atomicAdd(&g_cntN[n4.y], 1);
            atomicAdd(&g_cntN[n4.z], 1); atomicAdd(&g_cntN[n4.w], 1);
            atomicAdd(&g_cntE[h4.x], 1); atomicAdd(&g_cntE[h4.y], 1);
            atomicAdd(&g_cntE[h4.z], 1); atomicAdd(&g_cntE[h4.w], 1);
        } else {
            for (int j = j0; j < nnz; j++) {
                atomicAdd(&g_cntN[node[j]], 1);
                atomicAdd(&g_cntE[hedge[j]], 1);
            }
        }
    }
}

__device__ __forceinline__ void alloc_ranges(const int* __restrict__ cnt, int* __restrict__ off,
                                             int* total, int n, int gwarp, int nwarps, int lane) {
    for (int j0 = gwarp * 32; j0 < n; j0 += nwarps * 32) {
        int j = j0 + lane;
        int c = (j < n) ? cnt[j] : 0;
        int x = c;
        #pragma unroll
        for (int o = 1; o < 32; o <<= 1) {
            int y = __shfl_up_sync(0xffffffffu, x, o);
            if (lane >= o) x += y;
        }
        int wtot = __shfl_sync(0xffffffffu, x, 31);
        int base = 0;
        if (lane == 0) base = atomicAdd(total, wtot);
        base = __shfl_sync(0xffffffffu, base, 0);
        if (j < n) off[j] = base + x - c;
    }
}

__global__ void alloc_kernel(int N, int E) {
    int t = blockIdx.x * blockDim.x + threadIdx.x;
    int gwarp = t >> 5, lane = t & 31;
    int nwarps = (gridDim.x * blockDim.x) >> 5;
    alloc_ranges(g_cntN, g_offN, &g_totN, N, gwarp, nwarps, lane);
    alloc_ranges(g_cntE, g_offE, &g_totE, E, gwarp, nwarps, lane);
}

__global__ void scatter_kernel(const int* __restrict__ node, const int* __restrict__ hedge, int nnz) {
    int t = blockIdx.x * blockDim.x + threadIdx.x;
    int stride4 = gridDim.x * blockDim.x * 4;
    for (int j0 = t * 4; j0 < nnz; j0 += stride4) {
        if (j0 + 3 < nnz) {
            int4 n4 = *(const int4*)&node[j0];
            int4 h4 = *(const int4*)&hedge[j0];
            g_csrN[g_offN[n4.x] + atomicAdd(&g_curN[n4.x], 1)] = j0 + 0;
            g_csrN[g_offN[n4.y] + atomicAdd(&g_curN[n4.y], 1)] = j0 + 1;
            g_csrN[g_offN[n4.z] + atomicAdd(&g_curN[n4.z], 1)] = j0 + 2;
            g_csrN[g_offN[n4.w] + atomicAdd(&g_curN[n4.w], 1)] = j0 + 3;
            g_csrE[g_offE[h4.x] + atomicAdd(&g_curE[h4.x], 1)] = j0 + 0;
            g_csrE[g_offE[h4.y] + atomicAdd(&g_curE[h4.y], 1)] = j0 + 1;
            g_csrE[g_offE[h4.z] + atomicAdd(&g_curE[h4.z], 1)] = j0 + 2;
            g_csrE[g_offE[h4.w] + atomicAdd(&g_curE[h4.w], 1)] = j0 + 3;
        } else {
            for (int j = j0; j < nnz; j++) {
                int n = node[j], h = hedge[j];
                g_csrN[g_offN[n] + atomicAdd(&g_curN[n], 1)] = j;
                g_csrE[g_offE[h] + atomicAdd(&g_curE[h], 1)] = j;
            }
        }
    }
}

// ---------------- tiled fp32 GEMM (round-5 version): C[M,N] = A[M,K] @ B[K,N] ----------------
template <int BM, int BN, int BK, int TM, int TN>
__global__ __launch_bounds__(256) void sgemm_kernel(const float* __restrict__ A,
                                                    const float* __restrict__ B,
                                                    float* __restrict__ C, int M, int N, int K) {
    constexpr int THREADS = (BM / TM) * (BN / TN);
    __shared__ float As[BK][BM];
    __shared__ float Bs[BK][BN];
    int tid = threadIdx.x;
    int tx = tid % (BN / TN);
    int ty = tid / (BN / TN);
    int rowBase = blockIdx.x * BM;
    int colBase = blockIdx.y * BN;
    float acc[TM][TN] = {};
    for (int kt = 0; kt < K; kt += BK) {
        #pragma unroll
        for (int l = tid; l < BM * BK / 4; l += THREADS) {
            int r = l / (BK / 4), c4 = l % (BK / 4);
            int gr = rowBase + r;
            float4 v = make_float4(0.f, 0.f, 0.f, 0.f);
            if (gr < M) v = *(const float4*)&A[(size_t)gr * K + kt + c4 * 4];
            As[c4 * 4 + 0][r] = v.x;
            As[c4 * 4 + 1][r] = v.y;
            As[c4 * 4 + 2][r] = v.z;
            As[c4 * 4 + 3][r] = v.w;
        }
        #pragma unroll
        for (int l = tid; l < BK * BN / 4; l += THREADS) {
            int r = l / (BN / 4), c4 = l % (BN / 4);
            *(float4*)&Bs[r][c4 * 4] = *(const float4*)&B[(size_t)(kt + r) * N + colBase + c4 * 4];
        }
        __syncthreads();
        #pragma unroll
        for (int k = 0; k < BK; k++) {
            float ar[TM], br[TN];
            #pragma unroll
            for (int i = 0; i < TM; i++) ar[i] = As[k][ty * TM + i];
            #pragma unroll
            for (int j = 0; j < TN; j++) br[j] = Bs[k][tx * TN + j];
            #pragma unroll
            for (int i = 0; i < TM; i++)
                #pragma unroll
                for (int j = 0; j < TN; j++) acc[i][j] += ar[i] * br[j];
        }
        __syncthreads();
    }
    #pragma unroll
    for (int i = 0; i < TM; i++) {
        int gr = rowBase + ty * TM + i;
        if (gr < M) {
            #pragma unroll
            for (int j4 = 0; j4 < TN / 4; j4++) {
                float4 v = make_float4(acc[i][j4 * 4 + 0], acc[i][j4 * 4 + 1],
                                       acc[i][j4 * 4 + 2], acc[i][j4 * 4 + 3]);
                *(float4*)&C[(size_t)gr * N + colBase + tx * TN + j4 * 4] = v;
            }
        }
    }
}

// ---------------- fold att into W1 ----------------
__global__ void attmat_kernel(const float* __restrict__ W1, const float* __restrict__ att) {
    int t = threadIdx.x;           // 512 threads
    int k = t >> 2, h = t & 3;
    const float* wrow = &W1[k * 256 + h * 64];
    const float* a1 = &att[h * 128];
    const float* a2 = &att[h * 128 + 64];
    float s1 = 0.f, s2 = 0.f;
    #pragma unroll
    for (int f = 0; f < 64; f++) {
        float w = wrow[f];
        s1 += w * a1[f];
        s2 += w * a2[f];
    }
    g_A1[k * 4 + h] = s1;
    g_A2[k * 4 + h] = s2;
}

// ---------------- attention logits: ax = x @ A1, ae = hat @ A2 ----------------
__global__ __launch_bounds__(256) void axae_kernel(const float* __restrict__ x,
                                                   const float* __restrict__ hat, int N, int E) {
    __shared__ float sA1[128 * 4], sA2[128 * 4];
    int tid = threadIdx.x;
    for (int i = tid; i < 512; i += 256) { sA1[i] = g_A1[i]; sA2[i] = g_A2[i]; }
    __syncthreads();
    int r = blockIdx.x * 256 + tid;
    if (r >= N + E) return;
    bool isNode = r < N;
    const float4* row = (const float4*)(isNode ? &x[(size_t)r * 128] : &hat[(size_t)(r - N) * 128]);
    const float* Am = isNode ? sA1 : sA2;
    float acc0 = 0.f, acc1 = 0.f, acc2 = 0.f, acc3 = 0.f;
    #pragma unroll
    for (int k4 = 0; k4 < 32; k4++) {
        float4 v = row[k4];
        const float* a = &Am[k4 * 16];
        acc0 += v.x * a[0];  acc1 += v.x * a[1];  acc2 += v.x * a[2];  acc3 += v.x * a[3];
        acc0 += v.y * a[4];  acc1 += v.y * a[5];  acc2 += v.y * a[6];  acc3 += v.y * a[7];
        acc0 += v.z * a[8];  acc1 += v.z * a[9];  acc2 += v.z * a[10]; acc3 += v.z * a[11];
        acc0 += v.w * a[12]; acc1 += v.w * a[13]; acc2 += v.w * a[14]; acc3 += v.w * a[15];
    }
    float* dst = isNode ? &g_ax[r * 4] : &g_ae[(r - N) * 4];
    dst[0] = acc0; dst[1] = acc1; dst[2] = acc2; dst[3] = acc3;
}

// ---------------- conv1 edge stage: segment softmax + propagate 1 ----------------
#define ECAP 1024
__global__ __launch_bounds__(256) void edge1_kernel(const int* __restrict__ nodeIdx) {
    int e = blockIdx.x;
    int tid = threadIdx.x;
    int lane = tid & 31, warp = tid >> 5;
    int beg = g_offE[e];
    int k = g_cntE[e];
    float aeh[4];
    #pragma unroll
    for (int h = 0; h < 4; h++) aeh[h] = g_ae[e * 4 + h];

    __shared__ int snode[ECAP];
    __shared__ int sidx[ECAP];
    __shared__ float slog[ECAP * 4];
    __shared__ float4 racc[256];
    __shared__ float wr[8][4];
    __shared__ float smax[4], sinv[4];

    int g = tid >> 6, f4 = tid & 63, hh = f4 >> 4;
    float Binv = k > 0 ? 1.f / (float)k : 0.f;
    float4 acc = make_float4(0.f, 0.f, 0.f, 0.f);
    const float4* xh4 = (const float4*)g_xh;

    if (k <= ECAP) {
        float lmax[4] = {-1e30f, -1e30f, -1e30f, -1e30f};
        for (int j = tid; j < k; j += 256) {
            int i = g_csrE[beg + j];
            int n = nodeIdx[i];
            sidx[j] = i;
            snode[j] = n;
            #pragma unroll
            for (int h = 0; h < 4; h++) {
                float z = g_ax[n * 4 + h] + aeh[h];
                z = z > 0.f ? z : 0.2f * z;
                slog[j * 4 + h] = z;
                lmax[h] = fmaxf(lmax[h], z);
            }
        }
        #pragma unroll
        for (int o = 16; o; o >>= 1)
            #pragma unroll
            for (int h = 0; h < 4; h++)
                lmax[h] = fmaxf(lmax[h], __shfl_xor_sync(0xffffffffu, lmax[h], o));
        if (lane == 0)
            #pragma unroll
            for (int h = 0; h < 4; h++) wr[warp][h] = lmax[h];
        __syncthreads();
        if (tid < 4) {
            float r = wr[0][tid];
            #pragma unroll
            for (int w2 = 1; w2 < 8; w2++) r = fmaxf(r, wr[w2][tid]);
            smax[tid] = r;
        }
        __syncthreads();

        float lsum[4] = {0.f, 0.f, 0.f, 0.f};
        for (int j = tid; j < k; j += 256) {
            #pragma unroll
            for (int h = 0; h < 4; h++) {
                float ex = __expf(slog[j * 4 + h] - smax[h]);
                slog[j * 4 + h] = ex;
                lsum[h] += ex;
            }
        }
        #pragma unroll
        for (int o = 16; o; o >>= 1)
            #pragma unroll
            for (int h = 0; h < 4; h++) lsum[h] += __shfl_xor_sync(0xffffffffu, lsum[h], o);
        if (lane == 0)
            #pragma unroll
            for (int h = 0; h < 4; h++) wr[warp][h] = lsum[h];
        __syncthreads();
        if (tid < 4) {
            float r = wr[0][tid];
            #pragma unroll
            for (int w2 = 1; w2 < 8; w2++) r += wr[w2][tid];
            sinv[tid] = 1.f / (r + 1e-16f);
        }
        __syncthreads();

        for (int j = tid; j < k; j += 256) {
            float4 a;
            a.x = slog[j * 4 + 0] * sinv[0];
            a.y = slog[j * 4 + 1] * sinv[1];
            a.z = slog[j * 4 + 2] * sinv[2];
            a.w = slog[j * 4 + 3] * sinv[3];
            slog[j * 4 + 0] = a.x; slog[j * 4 + 1] = a.y;
            slog[j * 4 + 2] = a.z; slog[j * 4 + 3] = a.w;
            ((float4*)g_alpha)[sidx[j]] = a;
        }
        __syncthreads();

        for (int j = g; j < k; j += 4) {
            float a = slog[j * 4 + hh];
            float4 xv = xh4[snode[j] * 64 + f4];
            acc.x += a * xv.x; acc.y += a * xv.y; acc.z += a * xv.z; acc.w += a * xv.w;
        }
    } else {
        float lmax[4] = {-1e30f, -1e30f, -1e30f, -1e30f};
        for (int j = tid; j < k; j += 256) {
            int i = g_csrE[beg + j];
            int n = nodeIdx[i];
            #pragma unroll
            for (int h = 0; h < 4; h++) {
                float z = g_ax[n * 4 + h] + aeh[h];
                z = z > 0.f ? z : 0.2f * z;
                g_alpha[i * 4 + h] = z;
                lmax[h] = fmaxf(lmax[h], z);
            }
        }
        #pragma unroll
        for (int o = 16; o; o >>= 1)
            #pragma unroll
            for (int h = 0; h < 4; h++)
                lmax[h] = fmaxf(lmax[h], __shfl_xor_sync(0xffffffffu, lmax[h], o));
        if (lane == 0)
            #pragma unroll
            for (int h = 0; h < 4; h++) wr[warp][h] = lmax[h];
        __syncthreads();
        if (tid < 4) {
            float r = wr[0][tid];
            #pragma unroll
            for (int w2 = 1; w2 < 8; w2++) r = fmaxf(r, wr[w2][tid]);
            smax[tid] = r;
        }
        __syncthreads();
        float lsum[4] = {0.f, 0.f, 0.f, 0.f};
        for (int j = tid; j < k; j += 256) {
            int i = g_csrE[beg + j];
            #pragma unroll
            for (int h = 0; h < 4; h++) {
                float ex = __expf(g_alpha[i * 4 + h] - smax[h]);
                g_alpha[i * 4 + h] = ex;
                lsum[h] += ex;
            }
        }
        #pragma unroll
        for (int o = 16; o; o >>= 1)
            #pragma unroll
            for (int h = 0; h < 4; h++) lsum[h] += __shfl_xor_sync(0xffffffffu, lsum[h], o);
        if (lane == 0)
            #pragma unroll
            for (int h = 0; h < 4; h++) wr[warp][h] = lsum[h];
        __syncthreads();
        if (tid < 4) {
            float r = wr[0][tid];
            #pragma unroll
            for (int w2 = 1; w2 < 8; w2++) r += wr[w2][tid];
            sinv[tid] = 1.f / (r + 1e-16f);
        }
        __syncthreads();
        for (int j = tid; j < k; j += 256) {
            int i = g_csrE[beg + j];
            #pragma unroll
            for (int h = 0; h < 4; h++) g_alpha[i * 4 + h] *= sinv[h];
        }
        __syncthreads();
        for (int base = 0; base < k; base += ECAP) {
            int c = min(ECAP, k - base);
            __syncthreads();
            for (int j = tid; j < c; j += 256) {
                int i = g_csrE[beg + base + j];
                snode[j] = nodeIdx[i];
                ((float4*)slog)[j] = ((const float4*)g_alpha)[i];
            }
            __syncthreads();
            for (int j = g; j < c; j += 4) {
                float a = slog[j * 4 + hh];
                float4 xv = xh4[snode[j] * 64 + f4];
                acc.x += a * xv.x; acc.y += a * xv.y; acc.z += a * xv.z; acc.w += a * xv.w;
            }
        }
    }

    racc[tid] = acc;
    __syncthreads();
    if (tid < 64) {
        float4 a = racc[tid], b = racc[tid + 64], c2 = racc[tid + 128], d2 = racc[tid + 192];
        float4 r;
        r.x = (a.x + b.x + c2.x + d2.x) * Binv;
        r.y = (a.y + b.y + c2.y + d2.y) * Binv;
        r.z = (a.z + b.z + c2.z + d2.z) * Binv;
        r.w = (a.w + b.w + c2.w + d2.w) * Binv;
        ((float4*)g_eh)[e * 64 + tid] = r;
    }
}

__device__ __forceinline__ float eluf(float x) { return x > 0.f ? x : expm1f(x); }

// ---------------- fused conv1 node stage + conv2 GEMM ----------------
// Persistent blocks; W2 transposed in dynamic smem [64][260] (conflict-free).
// Per node: gather (alpha * eh), reduce, + b1, elu -> hrow (smem) -> hrow @ W2 -> g_xh2.
__global__ __launch_bounds__(256) void node1_fused_kernel(const int* __restrict__ hedgeIdx,
                                                          const float* __restrict__ b1,
                                                          const float* __restrict__ W2, int N) {
    extern __shared__ float sW2[];     // [64][260]: sW2[j*260 + k] = W2[k*64 + j]
    __shared__ float4 racc[256];
    __shared__ float4 shrow4[64];
    float* shrow = (float*)shrow4;

    int tid = threadIdx.x;
    // stage W2 transposed (once per block)
    for (int idx = tid; idx < 256 * 64; idx += 256) {
        int k = idx >> 6, j = idx & 63;
        sW2[j * 260 + k] = W2[idx];
    }
    __syncthreads();

    int g = tid >> 6, f4 = tid & 63, h = f4 >> 4;
    int jj = tid >> 2, p = tid & 3;          // gemm phase mapping
    const float4* eh4 = (const float4*)g_eh;

    for (int n = blockIdx.x; n < N; n += gridDim.x) {
        int beg = g_offN[n];
        int d = g_cntN[n];
        int end = beg + d;
        float Dinv = d > 0 ? 1.f / (float)d : 0.f;
        float4 acc = make_float4(0.f, 0.f, 0.f, 0.f);
        for (int j = beg + g; j < end; j += 4) {
            int i = g_csrN[j];
            int e = hedgeIdx[i];
            float a = g_alpha[i * 4 + h];
            float4 ev = eh4[e * 64 + f4];
            acc.x += a * ev.x; acc.y += a * ev.y; acc.z += a * ev.z; acc.w += a * ev.w;
        }
        racc[tid] = acc;
        __syncthreads();
        if (tid < 64) {
            float4 a = racc[tid], b = racc[tid + 64], c2 = racc[tid + 128], d2 = racc[tid + 192];
            float4 bv = ((const float4*)b1)[tid];
            float4 r;
            r.x = eluf((a.x + b.x + c2.x + d2.x) * Dinv + bv.x);
            r.y = eluf((a.y + b.y + c2.y + d2.y) * Dinv + bv.y);
            r.z = eluf((a.z + b.z + c2.z + d2.z) * Dinv + bv.z);
            r.w = eluf((a.w + b.w + c2.w + d2.w) * Dinv + bv.w);
            shrow4[tid] = r;
        }
        __syncthreads();
        // gemm: xh2[n][jj] = sum_k hrow[k] * W2[k][jj]; thread (jj,p) covers k = p+4s
        const float* wrow = &sW2[jj * 260];
        float val = 0.f;
        #pragma unroll
        for (int s = 0; s < 64; s++) {
            int k = p + 4 * s;
            val += shrow[k] * wrow[k];
        }
        val += __shfl_xor_sync(0xffffffffu, val, 1);
        val += __shfl_xor_sync(0xffffffffu, val, 2);
        if (p == 0) g_xh2[(size_t)n * 64 + jj] = val;
        __syncthreads();
    }
}

// ---------------- conv2 edge stage ----------------
__global__ __launch_bounds__(256) void edge2_kernel(const int* __restrict__ nodeIdx) {
    int e = blockIdx.x;
    int tid = threadIdx.x;
    int beg = g_offE[e];
    int k = g_cntE[e];
    int end = beg + k;
    float Binv = k > 0 ? 1.f / (float)k : 0.f;
    int g = tid >> 6, f = tid & 63;
    float acc = 0.f;
    for (int j = beg + g; j < end; j += 4) {
        int i = g_csrE[j];
        int n = nodeIdx[i];
        acc += g_xh2[(size_t)n * 64 + f];
    }
    __shared__ float racc[256];
    racc[tid] = acc;
    __syncthreads();
    if (tid < 64)
        g_eh2[e * 64 + tid] = (racc[tid] + racc[tid + 64] + racc[tid + 128] + racc[tid + 192]) * Binv;
}

// ---------------- conv2 node stage: warp-per-node ----------------
__global__ __launch_bounds__(256) void node2_kernel(const int* __restrict__ hedgeIdx,
                                                    const float* __restrict__ b2,
                                                    float* __restrict__ out, int N) {
    int warp = threadIdx.x >> 5, lane = threadIdx.x & 31;
    int n = blockIdx.x * 8 + warp;
    if (n >= N) return;
    int beg = g_offN[n];
    int d = g_cntN[n];
    float Dinv = d > 0 ? 1.f / (float)d : 0.f;
    const float2* eh2 = (const float2*)g_eh2;
    float ax = 0.f, ay = 0.f;
    int j = beg, end = beg + d;
    for (; j + 1 < end; j += 2) {
        int i0 = g_csrN[j], i1 = g_csrN[j + 1];
        int e0 = hedgeIdx[i0], e1 = hedgeIdx[i1];
        float2 v0 = eh2[e0 * 32 + lane];
        float2 v1 = eh2[e1 * 32 + lane];
        ax += v0.x + v1.x; ay += v0.y + v1.y;
    }
    if (j < end) {
        int i = g_csrN[j];
        int e = hedgeIdx[i];
        float2 v = eh2[e * 32 + lane];
        ax += v.x; ay += v.y;
    }
    float2 bb = ((const float2*)b2)[lane];
    ((float2*)out)[(size_t)n * 32 + lane] = make_float2(ax * Dinv + bb.x, ay * Dinv + bb.y);
}

// ---------------- launch ----------------
extern "C" void kernel_launch(void* const* d_in, const int* in_sizes, int n_in,
                              void* d_out, int out_size) {
    const float* x    = (const float*)d_in[0];
    const int*   ei   = (const int*)d_in[1];
    const float* hat  = (const float*)d_in[2];
    const float* W1   = (const float*)d_in[3];
    const float* att1 = (const float*)d_in[4];
    const float* b1   = (const float*)d_in[5];
    const float* W2   = (const float*)d_in[6];
    const float* b2   = (const float*)d_in[7];
    float* out = (float*)d_out;

    int N   = in_sizes[0] / 128;
    int NNZ = in_sizes[1] / 2;
    int E   = in_sizes[2] / 128;
    const int* node  = ei;
    const int* hedge = ei + NNZ;

    float *p_xh;
    cudaGetSymbolAddress((void**)&p_xh, g_xh);

    const int SMEM_W2 = 64 * 260 * 4;   // 66560 B dynamic
    cudaFuncSetAttribute(node1_fused_kernel, cudaFuncAttributeMaxDynamicSharedMemorySize, SMEM_W2);

    // launch idx:            0            1        2       3 (profiled)  4
    zero_counts_kernel<<<128, 256>>>(N, E);
    count_kernel<<<480, 256>>>(node, hedge, NNZ);
    alloc_kernel<<<64, 256>>>(N, E);
    sgemm_kernel<128, 128, 16, 8, 8><<<dim3((N + 127) / 128, 2), 256>>>(x, W1, p_xh, N, 256, 128);
    scatter_kernel<<<480, 256>>>(node, hedge, NNZ);

    // attention logits via folded att
    attmat_kernel<<<1, 512>>>(W1, att1);
    axae_kernel<<<(N + E + 255) / 256, 256>>>(x, hat, N, E);

    // conv1: softmax + propagate 1
    edge1_kernel<<<E, 256>>>(node);
    // conv1 node stage fused with conv2 GEMM (persistent, 3 CTA/SM)
    node1_fused_kernel<<<444, 256, SMEM_W2>>>(hedge, b1, W2, N);

    // conv2 propagates
    edge2_kernel<<<E, 256>>>(node);
    node2_kernel<<<(N + 7) / 8, 256>>>(hedge, b2, out, N);
}

// round 8
// speedup vs baseline: 1.6876x; 1.6876x over previous
#include <cuda_runtime.h>
#include <math.h>
#include <cstdint>

#define MAXN   50000
#define MAXE   10000
#define MAXNNZ 600000

// ---------------- scratch (static __device__, no allocations) ----------------
__device__ float g_xh[MAXN * 256];    // x @ W1
__device__ float g_ax[MAXN * 4];
__device__ float g_ae[MAXE * 4];
__device__ float g_A1[128 * 4];
__device__ float g_A2[128 * 4];
__device__ float g_alpha[MAXNNZ * 4];
__device__ float g_eh[MAXE * 256];
__device__ float g_h[MAXN * 256];
__device__ float g_xh2[MAXN * 64];
__device__ float g_eh2[MAXE * 64];
__device__ int g_cntN[MAXN], g_cntE[MAXE];
__device__ int g_curN[MAXN], g_curE[MAXE];
__device__ int g_offN[MAXN], g_offE[MAXE];
__device__ int g_csrN[MAXNNZ], g_csrE[MAXNNZ];
__device__ int g_totN, g_totE;

// ---------------- CSR construction ----------------
__global__ void zero_counts_kernel(int N, int E) {
    int i = blockIdx.x * blockDim.x + threadIdx.x;
    int s = gridDim.x * blockDim.x;
    if (i == 0) { g_totN = 0; g_totE = 0; }
    for (int j = i; j < N; j += s) { g_cntN[j] = 0; g_curN[j] = 0; }
    for (int j = i; j < E; j += s) { g_cntE[j] = 0; g_curE[j] = 0; }
}

__global__ void count_kernel(const int* __restrict__ node, const int* __restrict__ hedge, int nnz) {
    int t = blockIdx.x * blockDim.x + threadIdx.x;
    int stride4 = gridDim.x * blockDim.x * 4;
    for (int j0 = t * 4; j0 < nnz; j0 += stride4) {
        if (j0 + 3 < nnz) {
            int4 n4 = *(const int4*)&node[j0];
            int4 h4 = *(const int4*)&hedge[j0];
            atomicAdd(&g_cntN[n4.x], 1); atomicAdd(&g_cntN[n4.y], 1);
            atomicAdd(&g_cntN[n4.z], 1); atomicAdd(&g_cntN[n4.w], 1);
            atomicAdd(&g_cntE[h4.x], 1); atomicAdd(&g_cntE[h4.y], 1);
            atomicAdd(&g_cntE[h4.z], 1); atomicAdd(&g_cntE[h4.w], 1);
        } else {
            for (int j = j0; j < nnz; j++) {
                atomicAdd(&g_cntN[node[j]], 1);
                atomicAdd(&g_cntE[hedge[j]], 1);
            }
        }
    }
}

__device__ __forceinline__ void alloc_ranges(const int* __restrict__ cnt, int* __restrict__ off,
                                             int* total, int n, int gwarp, int nwarps, int lane) {
    for (int j0 = gwarp * 32; j0 < n; j0 += nwarps * 32) {
        int j = j0 + lane;
        int c = (j < n) ? cnt[j] : 0;
        int x = c;
        #pragma unroll
        for (int o = 1; o < 32; o <<= 1) {
            int y = __shfl_up_sync(0xffffffffu, x, o);
            if (lane >= o) x += y;
        }
        int wtot = __shfl_sync(0xffffffffu, x, 31);
        int base = 0;
        if (lane == 0) base = atomicAdd(total, wtot);
        base = __shfl_sync(0xffffffffu, base, 0);
        if (j < n) off[j] = base + x - c;
    }
}

__global__ void alloc_kernel(int N, int E) {
    int t = blockIdx.x * blockDim.x + threadIdx.x;
    int gwarp = t >> 5, lane = t & 31;
    int nwarps = (gridDim.x * blockDim.x) >> 5;
    alloc_ranges(g_cntN, g_offN, &g_totN, N, gwarp, nwarps, lane);
    alloc_ranges(g_cntE, g_offE, &g_totE, E, gwarp, nwarps, lane);
}

__global__ void scatter_kernel(const int* __restrict__ node, const int* __restrict__ hedge, int nnz) {
    int t = blockIdx.x * blockDim.x + threadIdx.x;
    int stride4 = gridDim.x * blockDim.x * 4;
    for (int j0 = t * 4; j0 < nnz; j0 += stride4) {
        if (j0 + 3 < nnz) {
            int4 n4 = *(const int4*)&node[j0];
            int4 h4 = *(const int4*)&hedge[j0];
            g_csrN[g_offN[n4.x] + atomicAdd(&g_curN[n4.x], 1)] = j0 + 0;
            g_csrN[g_offN[n4.y] + atomicAdd(&g_curN[n4.y], 1)] = j0 + 1;
            g_csrN[g_offN[n4.z] + atomicAdd(&g_curN[n4.z], 1)] = j0 + 2;
            g_csrN[g_offN[n4.w] + atomicAdd(&g_curN[n4.w], 1)] = j0 + 3;
            g_csrE[g_offE[h4.x] + atomicAdd(&g_curE[h4.x], 1)] = j0 + 0;
            g_csrE[g_offE[h4.y] + atomicAdd(&g_curE[h4.y], 1)] = j0 + 1;
            g_csrE[g_offE[h4.z] + atomicAdd(&g_curE[h4.z], 1)] = j0 + 2;
            g_csrE[g_offE[h4.w] + atomicAdd(&g_curE[h4.w], 1)] = j0 + 3;
        } else {
            for (int j = j0; j < nnz; j++) {
                int n = node[j], h = hedge[j];
                g_csrN[g_offN[n] + atomicAdd(&g_curN[n], 1)] = j;
                g_csrE[g_offE[h] + atomicAdd(&g_curE[h], 1)] = j;
            }
        }
    }
}

// ---------------- tiled fp32 GEMM (round-5 version): C[M,N] = A[M,K] @ B[K,N] ----------------
template <int BM, int BN, int BK, int TM, int TN>
__global__ __launch_bounds__(256) void sgemm_kernel(const float* __restrict__ A,
                                                    const float* __restrict__ B,
                                                    float* __restrict__ C, int M, int N, int K) {
    constexpr int THREADS = (BM / TM) * (BN / TN);
    __shared__ float As[BK][BM];
    __shared__ float Bs[BK][BN];
    int tid = threadIdx.x;
    int tx = tid % (BN / TN);
    int ty = tid / (BN / TN);
    int rowBase = blockIdx.x * BM;
    int colBase = blockIdx.y * BN;
    float acc[TM][TN] = {};
    for (int kt = 0; kt < K; kt += BK) {
        #pragma unroll
        for (int l = tid; l < BM * BK / 4; l += THREADS) {
            int r = l / (BK / 4), c4 = l % (BK / 4);
            int gr = rowBase + r;
            float4 v = make_float4(0.f, 0.f, 0.f, 0.f);
            if (gr < M) v = *(const float4*)&A[(size_t)gr * K + kt + c4 * 4];
            As[c4 * 4 + 0][r] = v.x;
            As[c4 * 4 + 1][r] = v.y;
            As[c4 * 4 + 2][r] = v.z;
            As[c4 * 4 + 3][r] = v.w;
        }
        #pragma unroll
        for (int l = tid; l < BK * BN / 4; l += THREADS) {
            int r = l / (BN / 4), c4 = l % (BN / 4);
            *(float4*)&Bs[r][c4 * 4] = *(const float4*)&B[(size_t)(kt + r) * N + colBase + c4 * 4];
        }
        __syncthreads();
        #pragma unroll
        for (int k = 0; k < BK; k++) {
            float ar[TM], br[TN];
            #pragma unroll
            for (int i = 0; i < TM; i++) ar[i] = As[k][ty * TM + i];
            #pragma unroll
            for (int j = 0; j < TN; j++) br[j] = Bs[k][tx * TN + j];
            #pragma unroll
            for (int i = 0; i < TM; i++)
                #pragma unroll
                for (int j = 0; j < TN; j++) acc[i][j] += ar[i] * br[j];
        }
        __syncthreads();
    }
    #pragma unroll
    for (int i = 0; i < TM; i++) {
        int gr = rowBase + ty * TM + i;
        if (gr < M) {
            #pragma unroll
            for (int j4 = 0; j4 < TN / 4; j4++) {
                float4 v = make_float4(acc[i][j4 * 4 + 0], acc[i][j4 * 4 + 1],
                                       acc[i][j4 * 4 + 2], acc[i][j4 * 4 + 3]);
                *(float4*)&C[(size_t)gr * N + colBase + tx * TN + j4 * 4] = v;
            }
        }
    }
}

// ---------------- fold att into W1 ----------------
__global__ void attmat_kernel(const float* __restrict__ W1, const float* __restrict__ att) {
    int t = threadIdx.x;           // 512 threads
    int k = t >> 2, h = t & 3;
    const float* wrow = &W1[k * 256 + h * 64];
    const float* a1 = &att[h * 128];
    const float* a2 = &att[h * 128 + 64];
    float s1 = 0.f, s2 = 0.f;
    #pragma unroll
    for (int f = 0; f < 64; f++) {
        float w = wrow[f];
        s1 += w * a1[f];
        s2 += w * a2[f];
    }
    g_A1[k * 4 + h] = s1;
    g_A2[k * 4 + h] = s2;
}

// ---------------- attention logits: ax = x @ A1, ae = hat @ A2 ----------------
__global__ __launch_bounds__(256) void axae_kernel(const float* __restrict__ x,
                                                   const float* __restrict__ hat, int N, int E) {
    __shared__ float sA1[128 * 4], sA2[128 * 4];
    int tid = threadIdx.x;
    for (int i = tid; i < 512; i += 256) { sA1[i] = g_A1[i]; sA2[i] = g_A2[i]; }
    __syncthreads();
    int r = blockIdx.x * 256 + tid;
    if (r >= N + E) return;
    bool isNode = r < N;
    const float4* row = (const float4*)(isNode ? &x[(size_t)r * 128] : &hat[(size_t)(r - N) * 128]);
    const float* Am = isNode ? sA1 : sA2;
    float acc0 = 0.f, acc1 = 0.f, acc2 = 0.f, acc3 = 0.f;
    #pragma unroll
    for (int k4 = 0; k4 < 32; k4++) {
        float4 v = row[k4];
        const float* a = &Am[k4 * 16];
        acc0 += v.x * a[0];  acc1 += v.x * a[1];  acc2 += v.x * a[2];  acc3 += v.x * a[3];
        acc0 += v.y * a[4];  acc1 += v.y * a[5];  acc2 += v.y * a[6];  acc3 += v.y * a[7];
        acc0 += v.z * a[8];  acc1 += v.z * a[9];  acc2 += v.z * a[10]; acc3 += v.z * a[11];
        acc0 += v.w * a[12]; acc1 += v.w * a[13]; acc2 += v.w * a[14]; acc3 += v.w * a[15];
    }
    float* dst = isNode ? &g_ax[r * 4] : &g_ae[(r - N) * 4];
    dst[0] = acc0; dst[1] = acc1; dst[2] = acc2; dst[3] = acc3;
}

// ---------------- conv1 edge stage: segment softmax + propagate 1 ----------------
#define ECAP 1024
__global__ __launch_bounds__(256) void edge1_kernel(const int* __restrict__ nodeIdx) {
    int e = blockIdx.x;
    int tid = threadIdx.x;
    int lane = tid & 31, warp = tid >> 5;
    int beg = g_offE[e];
    int k = g_cntE[e];
    float aeh[4];
    #pragma unroll
    for (int h = 0; h < 4; h++) aeh[h] = g_ae[e * 4 + h];

    __shared__ int snode[ECAP];
    __shared__ int sidx[ECAP];
    __shared__ float slog[ECAP * 4];
    __shared__ float4 racc[256];
    __shared__ float wr[8][4];
    __shared__ float smax[4], sinv[4];

    int g = tid >> 6, f4 = tid & 63, hh = f4 >> 4;
    float Binv = k > 0 ? 1.f / (float)k : 0.f;
    float4 acc = make_float4(0.f, 0.f, 0.f, 0.f);
    const float4* xh4 = (const float4*)g_xh;

    if (k <= ECAP) {
        float lmax[4] = {-1e30f, -1e30f, -1e30f, -1e30f};
        for (int j = tid; j < k; j += 256) {
            int i = g_csrE[beg + j];
            int n = nodeIdx[i];
            sidx[j] = i;
            snode[j] = n;
            #pragma unroll
            for (int h = 0; h < 4; h++) {
                float z = g_ax[n * 4 + h] + aeh[h];
                z = z > 0.f ? z : 0.2f * z;
                slog[j * 4 + h] = z;
                lmax[h] = fmaxf(lmax[h], z);
            }
        }
        #pragma unroll
        for (int o = 16; o; o >>= 1)
            #pragma unroll
            for (int h = 0; h < 4; h++)
                lmax[h] = fmaxf(lmax[h], __shfl_xor_sync(0xffffffffu, lmax[h], o));
        if (lane == 0)
            #pragma unroll
            for (int h = 0; h < 4; h++) wr[warp][h] = lmax[h];
        __syncthreads();
        if (tid < 4) {
            float r = wr[0][tid];
            #pragma unroll
            for (int w2 = 1; w2 < 8; w2++) r = fmaxf(r, wr[w2][tid]);
            smax[tid] = r;
        }
        __syncthreads();

        float lsum[4] = {0.f, 0.f, 0.f, 0.f};
        for (int j = tid; j < k; j += 256) {
            #pragma unroll
            for (int h = 0; h < 4; h++) {
                float ex = __expf(slog[j * 4 + h] - smax[h]);
                slog[j * 4 + h] = ex;
                lsum[h] += ex;
            }
        }
        #pragma unroll
        for (int o = 16; o; o >>= 1)
            #pragma unroll
            for (int h = 0; h < 4; h++) lsum[h] += __shfl_xor_sync(0xffffffffu, lsum[h], o);
        if (lane == 0)
            #pragma unroll
            for (int h = 0; h < 4; h++) wr[warp][h] = lsum[h];
        __syncthreads();
        if (tid < 4) {
            float r = wr[0][tid];
            #pragma unroll
            for (int w2 = 1; w2 < 8; w2++) r += wr[w2][tid];
            sinv[tid] = 1.f / (r + 1e-16f);
        }
        __syncthreads();

        for (int j = tid; j < k; j += 256) {
            float4 a;
            a.x = slog[j * 4 + 0] * sinv[0];
            a.y = slog[j * 4 + 1] * sinv[1];
            a.z = slog[j * 4 + 2] * sinv[2];
            a.w = slog[j * 4 + 3] * sinv[3];
            slog[j * 4 + 0] = a.x; slog[j * 4 + 1] = a.y;
            slog[j * 4 + 2] = a.z; slog[j * 4 + 3] = a.w;
            ((float4*)g_alpha)[sidx[j]] = a;
        }
        __syncthreads();

        for (int j = g; j < k; j += 4) {
            float a = slog[j * 4 + hh];
            float4 xv = xh4[snode[j] * 64 + f4];
            acc.x += a * xv.x; acc.y += a * xv.y; acc.z += a * xv.z; acc.w += a * xv.w;
        }
    } else {
        float lmax[4] = {-1e30f, -1e30f, -1e30f, -1e30f};
        for (int j = tid; j < k; j += 256) {
            int i = g_csrE[beg + j];
            int n = nodeIdx[i];
            #pragma unroll
            for (int h = 0; h < 4; h++) {
                float z = g_ax[n * 4 + h] + aeh[h];
                z = z > 0.f ? z : 0.2f * z;
                g_alpha[i * 4 + h] = z;
                lmax[h] = fmaxf(lmax[h], z);
            }
        }
        #pragma unroll
        for (int o = 16; o; o >>= 1)
            #pragma unroll
            for (int h = 0; h < 4; h++)
                lmax[h] = fmaxf(lmax[h], __shfl_xor_sync(0xffffffffu, lmax[h], o));
        if (lane == 0)
            #pragma unroll
            for (int h = 0; h < 4; h++) wr[warp][h] = lmax[h];
        __syncthreads();
        if (tid < 4) {
            float r = wr[0][tid];
            #pragma unroll
            for (int w2 = 1; w2 < 8; w2++) r = fmaxf(r, wr[w2][tid]);
            smax[tid] = r;
        }
        __syncthreads();
        float lsum[4] = {0.f, 0.f, 0.f, 0.f};
        for (int j = tid; j < k; j += 256) {
            int i = g_csrE[beg + j];
            #pragma unroll
            for (int h = 0; h < 4; h++) {
                float ex = __expf(g_alpha[i * 4 + h] - smax[h]);
                g_alpha[i * 4 + h] = ex;
                lsum[h] += ex;
            }
        }
        #pragma unroll
        for (int o = 16; o; o >>= 1)
            #pragma unroll
            for (int h = 0; h < 4; h++) lsum[h] += __shfl_xor_sync(0xffffffffu, lsum[h], o);
        if (lane == 0)
            #pragma unroll
            for (int h = 0; h < 4; h++) wr[warp][h] = lsum[h];
        __syncthreads();
        if (tid < 4) {
            float r = wr[0][tid];
            #pragma unroll
            for (int w2 = 1; w2 < 8; w2++) r += wr[w2][tid];
            sinv[tid] = 1.f / (r + 1e-16f);
        }
        __syncthreads();
        for (int j = tid; j < k; j += 256) {
            int i = g_csrE[beg + j];
            #pragma unroll
            for (int h = 0; h < 4; h++) g_alpha[i * 4 + h] *= sinv[h];
        }
        __syncthreads();
        for (int base = 0; base < k; base += ECAP) {
            int c = min(ECAP, k - base);
            __syncthreads();
            for (int j = tid; j < c; j += 256) {
                int i = g_csrE[beg + base + j];
                snode[j] = nodeIdx[i];
                ((float4*)slog)[j] = ((const float4*)g_alpha)[i];
            }
            __syncthreads();
            for (int j = g; j < c; j += 4) {
                float a = slog[j * 4 + hh];
                float4 xv = xh4[snode[j] * 64 + f4];
                acc.x += a * xv.x; acc.y += a * xv.y; acc.z += a * xv.z; acc.w += a * xv.w;
            }
        }
    }

    racc[tid] = acc;
    __syncthreads();
    if (tid < 64) {
        float4 a = racc[tid], b = racc[tid + 64], c2 = racc[tid + 128], d2 = racc[tid + 192];
        float4 r;
        r.x = (a.x + b.x + c2.x + d2.x) * Binv;
        r.y = (a.y + b.y + c2.y + d2.y) * Binv;
        r.z = (a.z + b.z + c2.z + d2.z) * Binv;
        r.w = (a.w + b.w + c2.w + d2.w) * Binv;
        ((float4*)g_eh)[e * 64 + tid] = r;
    }
}

__device__ __forceinline__ float eluf(float x) { return x > 0.f ? x : expm1f(x); }

// ---------------- conv1 node stage ----------------
__global__ __launch_bounds__(256) void node1_kernel(const int* __restrict__ hedgeIdx,
                                                    const float* __restrict__ b1) {
    int n = blockIdx.x;
    int tid = threadIdx.x;
    int beg = g_offN[n];
    int d = g_cntN[n];
    int end = beg + d;
    float Dinv = d > 0 ? 1.f / (float)d : 0.f;
    int g = tid >> 6, f4 = tid & 63, h = f4 >> 4;
    float4 acc = make_float4(0.f, 0.f, 0.f, 0.f);
    const float4* eh4 = (const float4*)g_eh;
    for (int j = beg + g; j < end; j += 4) {
        int i = g_csrN[j];
        int e = hedgeIdx[i];
        float a = g_alpha[i * 4 + h];
        float4 ev = eh4[e * 64 + f4];
        acc.x += a * ev.x; acc.y += a * ev.y; acc.z += a * ev.z; acc.w += a * ev.w;
    }
    __shared__ float4 racc[256];
    racc[tid] = acc;
    __syncthreads();
    if (tid < 64) {
        float4 a = racc[tid], b = racc[tid + 64], c2 = racc[tid + 128], d2 = racc[tid + 192];
        float4 bv = ((const float4*)b1)[tid];
        float4 r;
        r.x = eluf((a.x + b.x + c2.x + d2.x) * Dinv + bv.x);
        r.y = eluf((a.y + b.y + c2.y + d2.y) * Dinv + bv.y);
        r.z = eluf((a.z + b.z + c2.z + d2.z) * Dinv + bv.z);
        r.w = eluf((a.w + b.w + c2.w + d2.w) * Dinv + bv.w);
        ((float4*)g_h)[n * 64 + tid] = r;
    }
}

// ---------------- conv2 ----------------
__global__ __launch_bounds__(256) void edge2_kernel(const int* __restrict__ nodeIdx) {
    int e = blockIdx.x;
    int tid = threadIdx.x;
    int beg = g_offE[e];
    int k = g_cntE[e];
    int end = beg + k;
    float Binv = k > 0 ? 1.f / (float)k : 0.f;
    int g = tid >> 6, f = tid & 63;
    float acc = 0.f;
    for (int j = beg + g; j < end; j += 4) {
        int i = g_csrE[j];
        int n = nodeIdx[i];
        acc += g_xh2[(size_t)n * 64 + f];
    }
    __shared__ float racc[256];
    racc[tid] = acc;
    __syncthreads();
    if (tid < 64)
        g_eh2[e * 64 + tid] = (racc[tid] + racc[tid + 64] + racc[tid + 128] + racc[tid + 192]) * Binv;
}

// ---------------- conv2 node stage: warp-per-node ----------------
__global__ __launch_bounds__(256) void node2_kernel(const int* __restrict__ hedgeIdx,
                                                    const float* __restrict__ b2,
                                                    float* __restrict__ out, int N) {
    int warp = threadIdx.x >> 5, lane = threadIdx.x & 31;
    int n = blockIdx.x * 8 + warp;
    if (n >= N) return;
    int beg = g_offN[n];
    int d = g_cntN[n];
    float Dinv = d > 0 ? 1.f / (float)d : 0.f;
    const float2* eh2 = (const float2*)g_eh2;
    float ax = 0.f, ay = 0.f;
    int j = beg, end = beg + d;
    for (; j + 1 < end; j += 2) {
        int i0 = g_csrN[j], i1 = g_csrN[j + 1];
        int e0 = hedgeIdx[i0], e1 = hedgeIdx[i1];
        float2 v0 = eh2[e0 * 32 + lane];
        float2 v1 = eh2[e1 * 32 + lane];
        ax += v0.x + v1.x; ay += v0.y + v1.y;
    }
    if (j < end) {
        int i = g_csrN[j];
        int e = hedgeIdx[i];
        float2 v = eh2[e * 32 + lane];
        ax += v.x; ay += v.y;
    }
    float2 bb = ((const float2*)b2)[lane];
    ((float2*)out)[(size_t)n * 32 + lane] = make_float2(ax * Dinv + bb.x, ay * Dinv + bb.y);
}

// ---------------- launch ----------------
extern "C" void kernel_launch(void* const* d_in, const int* in_sizes, int n_in,
                              void* d_out, int out_size) {
    const float* x    = (const float*)d_in[0];
    const int*   ei   = (const int*)d_in[1];
    const float* hat  = (const float*)d_in[2];
    const float* W1   = (const float*)d_in[3];
    const float* att1 = (const float*)d_in[4];
    const float* b1   = (const float*)d_in[5];
    const float* W2   = (const float*)d_in[6];
    const float* b2   = (const float*)d_in[7];
    float* out = (float*)d_out;

    int N   = in_sizes[0] / 128;
    int NNZ = in_sizes[1] / 2;
    int E   = in_sizes[2] / 128;
    const int* node  = ei;
    const int* hedge = ei + NNZ;

    float *p_xh, *p_h, *p_xh2;
    cudaGetSymbolAddress((void**)&p_xh, g_xh);
    cudaGetSymbolAddress((void**)&p_h, g_h);
    cudaGetSymbolAddress((void**)&p_xh2, g_xh2);

    // lazy one-time side stream + events (host objects only; identical work every call)
    static cudaStream_t s1 = nullptr;
    static cudaEvent_t evFork = nullptr, evJoin = nullptr;
    if (s1 == nullptr) {
        cudaStreamCreateWithFlags(&s1, cudaStreamNonBlocking);
        cudaEventCreateWithFlags(&evFork, cudaEventDisableTiming);
        cudaEventCreateWithFlags(&evJoin, cudaEventDisableTiming);
    }

    // fork: side stream runs the GEMM + attention-logit chain concurrently
    // with the CSR build on the main stream.
    cudaEventRecord(evFork, 0);
    cudaStreamWaitEvent(s1, evFork, 0);

    // side stream (chain B): xh = x@W1 ; A1/A2 fold ; ax/ae logits
    sgemm_kernel<128, 128, 16, 8, 8><<<dim3((N + 127) / 128, 2), 256, 0, s1>>>(x, W1, p_xh, N, 256, 128);
    attmat_kernel<<<1, 512, 0, s1>>>(W1, att1);
    axae_kernel<<<(N + E + 255) / 256, 256, 0, s1>>>(x, hat, N, E);
    cudaEventRecord(evJoin, s1);

    // main stream (chain A): CSR build
    zero_counts_kernel<<<128, 256>>>(N, E);
    count_kernel<<<480, 256>>>(node, hedge, NNZ);
    alloc_kernel<<<64, 256>>>(N, E);
    scatter_kernel<<<480, 256>>>(node, hedge, NNZ);

    // join
    cudaStreamWaitEvent(0, evJoin, 0);

    // conv1: softmax + propagate 1 + node stage
    edge1_kernel<<<E, 256>>>(node);
    node1_kernel<<<N, 256>>>(hedge, b1);

    // conv2
    sgemm_kernel<128, 64, 16, 8, 4><<<dim3((N + 127) / 128, 1), 256>>>(p_h, W2, p_xh2, N, 64, 256);
    edge2_kernel<<<E, 256>>>(node);
    node2_kernel<<<(N + 7) / 8, 256>>>(hedge, b2, out, N);
}